// round 1
// baseline (speedup 1.0000x reference)
#include <cuda_runtime.h>
#include <math.h>

// Problem dims (fixed by the dataset)
#define DD    192           // hidden dim
#define HDIM  12            // head dim
#define NHEAD 16            // heads
#define SEQ   8192          // sequence length per batch
#define BATCH 16
#define NROWS (BATCH * SEQ) // 131072 total rows

// ---------------- scratch (static device globals; no runtime allocation) ---
__device__ float g_q[(size_t)NROWS * DD];
__device__ float g_k[(size_t)NROWS * DD];
__device__ float g_v[(size_t)NROWS * DD];
__device__ float g_ctx[(size_t)NROWS * DD];
// g_q is reused as the pre-LayerNorm buffer h after attention consumes q.

// ---------------- GEMM: out[r, c] = (sum_k A[r,k] * W[c,k] + bias[c]) * scale
//                                     (+ res[r,c] if res != nullptr)
// A: [NROWS, 192] row-major, W: [192, 192] row-major (out-dim major).
#define BM 64
#define BN 64
#define BK 64
#define PADS 68   // smem stride (words): 68*4B = 272B, 16B-aligned, breaks conflicts

__global__ __launch_bounds__(256)
void gemm_bias(const float* __restrict__ A, const float* __restrict__ W,
               const float* __restrict__ bias, const float* __restrict__ res,
               float* __restrict__ out, float scale)
{
    __shared__ float As[BK * PADS];
    __shared__ float Bs[BK * PADS];

    const int row0 = blockIdx.x * BM;
    const int col0 = blockIdx.y * BN;
    const int tid  = threadIdx.x;
    const int tx   = tid & 15;   // n direction (4 cols each)
    const int ty   = tid >> 4;   // m direction (4 rows each)

    float acc[4][4] = {};

    for (int k0 = 0; k0 < DD; k0 += BK) {
        // Stage A tile transposed: As[k][m]
        #pragma unroll
        for (int i = tid; i < BM * BK; i += 256) {
            int r  = i >> 6;      // 0..63
            int kk = i & 63;
            As[kk * PADS + r] = A[(size_t)(row0 + r) * DD + k0 + kk];
        }
        // Stage W tile transposed: Bs[k][n]
        #pragma unroll
        for (int i = tid; i < BN * BK; i += 256) {
            int r  = i >> 6;
            int kk = i & 63;
            Bs[kk * PADS + r] = W[(size_t)(col0 + r) * DD + k0 + kk];
        }
        __syncthreads();

        #pragma unroll 8
        for (int kk = 0; kk < BK; kk++) {
            float4 a4 = *(const float4*)&As[kk * PADS + ty * 4];
            float4 b4 = *(const float4*)&Bs[kk * PADS + tx * 4];
            float a[4] = {a4.x, a4.y, a4.z, a4.w};
            float b[4] = {b4.x, b4.y, b4.z, b4.w};
            #pragma unroll
            for (int i = 0; i < 4; i++)
                #pragma unroll
                for (int j = 0; j < 4; j++)
                    acc[i][j] += a[i] * b[j];
        }
        __syncthreads();
    }

    // Epilogue: bias, scale, optional residual; vectorized store
    #pragma unroll
    for (int i = 0; i < 4; i++) {
        int r = row0 + ty * 4 + i;
        int c0 = col0 + tx * 4;
        float4 o;
        float v0 = (acc[i][0] + bias[c0 + 0]) * scale;
        float v1 = (acc[i][1] + bias[c0 + 1]) * scale;
        float v2 = (acc[i][2] + bias[c0 + 2]) * scale;
        float v3 = (acc[i][3] + bias[c0 + 3]) * scale;
        if (res != nullptr) {
            const float4 rv = *(const float4*)&res[(size_t)r * DD + c0];
            v0 += rv.x; v1 += rv.y; v2 += rv.z; v3 += rv.w;
        }
        o.x = v0; o.y = v1; o.z = v2; o.w = v3;
        *(float4*)&out[(size_t)r * DD + c0] = o;
    }
}

// ---------------- banded attention: window d in [-2, 2] within each sequence
#define TS 16              // queries per block
#define KVROWS (TS + 4)    // staged key/value rows

__global__ __launch_bounds__(256)
void band_attn(const float* __restrict__ mask0)
{
    __shared__ float ks[KVROWS * DD];
    __shared__ float vs[KVROWS * DD];
    __shared__ float msk[KVROWS];

    const int chunk = blockIdx.x;
    const int b  = chunk / (SEQ / TS);
    const int s0 = (chunk % (SEQ / TS)) * TS;
    const int tid = threadIdx.x;

    // Stage k, v rows [s0-2, s0+TS+2) (zero-filled out of sequence range)
    for (int i4 = tid; i4 < KVROWS * (DD / 4); i4 += 256) {
        int r  = i4 / (DD / 4);
        int c4 = i4 % (DD / 4);
        int s  = s0 - 2 + r;
        float4 kv = make_float4(0.f, 0.f, 0.f, 0.f);
        float4 vv = make_float4(0.f, 0.f, 0.f, 0.f);
        if (s >= 0 && s < SEQ) {
            size_t off = (size_t)(b * SEQ + s) * DD + c4 * 4;
            kv = *(const float4*)&g_k[off];
            vv = *(const float4*)&g_v[off];
        }
        *(float4*)&ks[r * DD + c4 * 4] = kv;
        *(float4*)&vs[r * DD + c4 * 4] = vv;
    }
    if (tid < KVROWS) {
        int s = s0 - 2 + tid;
        msk[tid] = (s >= 0 && s < SEQ) ? mask0[b * SEQ + s] : 0.f;
    }
    __syncthreads();

    const int sl = tid >> 4;    // local query index 0..15
    const int h  = tid & 15;    // head
    const int s  = s0 + sl;

    // Load q (scaled at projection time)
    float q[HDIM];
    {
        const float* qp = &g_q[(size_t)(b * SEQ + s) * DD + h * HDIM];
        float4 q0 = *(const float4*)(qp + 0);
        float4 q1 = *(const float4*)(qp + 4);
        float4 q2 = *(const float4*)(qp + 8);
        q[0]=q0.x; q[1]=q0.y; q[2]=q0.z;  q[3]=q0.w;
        q[4]=q1.x; q[5]=q1.y; q[6]=q1.z;  q[7]=q1.w;
        q[8]=q2.x; q[9]=q2.y; q[10]=q2.z; q[11]=q2.w;
    }

    const float NEG = -3.402823466e38f;            // finfo(float32).min
    const float NINF = __int_as_float(0xff800000); // -inf

    float sc[5];
    #pragma unroll
    for (int d = 0; d < 5; d++) {
        int r = sl + d;                 // smem row of key s+d-2
        int skey = s + d - 2;
        const float* kp = &ks[r * DD + h * HDIM];
        float dot = 0.f;
        #pragma unroll
        for (int j = 0; j < HDIM; j++) dot += q[j] * kp[j];
        float fm = (msk[r] != 0.f) ? NEG : 0.f;
        sc[d] = (skey >= 0 && skey < SEQ) ? (dot + fm) : NINF;
    }

    float mx = sc[0];
    #pragma unroll
    for (int d = 1; d < 5; d++) mx = fmaxf(mx, sc[d]);
    float e[5], sum = 0.f;
    #pragma unroll
    for (int d = 0; d < 5; d++) { e[d] = expf(sc[d] - mx); sum += e[d]; }
    float inv = 1.f / sum;
    bool index_masked = (msk[sl + 2] < 0.f);

    float c[HDIM] = {};
    #pragma unroll
    for (int d = 0; d < 5; d++) {
        float p = index_masked ? 0.f : e[d] * inv;
        const float* vp = &vs[(sl + d) * DD + h * HDIM];
        #pragma unroll
        for (int j = 0; j < HDIM; j++) c[j] += p * vp[j];
    }

    float* op = &g_ctx[(size_t)(b * SEQ + s) * DD + h * HDIM];
    *(float4*)(op + 0) = make_float4(c[0], c[1], c[2],  c[3]);
    *(float4*)(op + 4) = make_float4(c[4], c[5], c[6],  c[7]);
    *(float4*)(op + 8) = make_float4(c[8], c[9], c[10], c[11]);
}

// ---------------- LayerNorm over the last dim (192), warp per row
__global__ __launch_bounds__(256)
void layernorm(const float* __restrict__ ln_g, const float* __restrict__ ln_b,
               float* __restrict__ out)
{
    const int row  = blockIdx.x * 8 + (threadIdx.x >> 5);
    const int lane = threadIdx.x & 31;

    const float* hp = &g_q[(size_t)row * DD];  // g_q holds h after gemm #4
    float h[6];
    float sum = 0.f;
    #pragma unroll
    for (int j = 0; j < 6; j++) { h[j] = hp[lane + j * 32]; sum += h[j]; }
    #pragma unroll
    for (int o = 16; o > 0; o >>= 1) sum += __shfl_xor_sync(0xffffffffu, sum, o);
    float mu = sum * (1.f / 192.f);

    float s2 = 0.f;
    #pragma unroll
    for (int j = 0; j < 6; j++) { float d = h[j] - mu; s2 += d * d; }
    #pragma unroll
    for (int o = 16; o > 0; o >>= 1) s2 += __shfl_xor_sync(0xffffffffu, s2, o);
    float invstd = rsqrtf(s2 * (1.f / 192.f) + 1e-12f);

    float* op = &out[(size_t)row * DD];
    #pragma unroll
    for (int j = 0; j < 6; j++) {
        int cc = lane + j * 32;
        op[cc] = (h[j] - mu) * invstd * ln_g[cc] + ln_b[cc];
    }
}

// ---------------- launch -------------------------------------------------
extern "C" void kernel_launch(void* const* d_in, const int* in_sizes, int n_in,
                              void* d_out, int out_size)
{
    const float* x     = (const float*)d_in[0];
    const float* mask0 = (const float*)d_in[1];
    const float* Wq    = (const float*)d_in[2];
    const float* bq    = (const float*)d_in[3];
    const float* Wk    = (const float*)d_in[4];
    const float* bk    = (const float*)d_in[5];
    const float* Wv    = (const float*)d_in[6];
    const float* bv    = (const float*)d_in[7];
    const float* Wo    = (const float*)d_in[8];
    const float* bo    = (const float*)d_in[9];
    const float* ln_g  = (const float*)d_in[10];
    const float* ln_b  = (const float*)d_in[11];
    float* out = (float*)d_out;

    float *pq, *pk, *pv, *pctx;
    cudaGetSymbolAddress((void**)&pq,   g_q);
    cudaGetSymbolAddress((void**)&pk,   g_k);
    cudaGetSymbolAddress((void**)&pv,   g_v);
    cudaGetSymbolAddress((void**)&pctx, g_ctx);

    const float qscale = 0.28867513459481287f;  // 1/sqrt(12)

    dim3 ggrid(NROWS / BM, DD / BN);            // (2048, 3)
    gemm_bias<<<ggrid, 256>>>(x,    Wq, bq, nullptr, pq, qscale);
    gemm_bias<<<ggrid, 256>>>(x,    Wk, bk, nullptr, pk, 1.0f);
    gemm_bias<<<ggrid, 256>>>(x,    Wv, bv, nullptr, pv, 1.0f);

    band_attn<<<BATCH * (SEQ / TS), 256>>>(mask0);

    gemm_bias<<<ggrid, 256>>>(pctx, Wo, bo, x,      pq, 1.0f);  // h -> g_q

    layernorm<<<NROWS / 8, 256>>>(ln_g, ln_b, out);
}

// round 2
// speedup vs baseline: 1.3068x; 1.3068x over previous
#include <cuda_runtime.h>
#include <math.h>
#include <stdint.h>

// Problem dims (fixed by the dataset)
#define DD    192           // hidden dim
#define HDIM  12            // head dim
#define SEQ   8192          // sequence length per batch
#define BATCH 16
#define NROWS (BATCH * SEQ) // 131072 total rows

// ---------------- scratch (static device globals; no runtime allocation) ---
__device__ float g_q[(size_t)NROWS * DD];
__device__ float g_k[(size_t)NROWS * DD];
__device__ float g_v[(size_t)NROWS * DD];
__device__ float g_ctx[(size_t)NROWS * DD];
// g_q is reused as the pre-LayerNorm buffer h after attention consumes q.

// ---------------- tensor-core GEMM (3xTF32 emulation of fp32) -------------
// out[r, c] = (sum_k A[r,k] * W[c,k] + bias[c]) * scale  (+ res[r,c] if res)
// A: [NROWS, 192] row-major, W: [192, 192] row-major (out-dim major).
#define BM 64
#define BN 64
#define BK 64
#define PADK 68  // smem row stride in words; (4m+k)%32 distinct for frag loads

__device__ __forceinline__ uint32_t f2tf32(float f) {
    uint32_t r;
    asm("cvt.rna.tf32.f32 %0, %1;" : "=r"(r) : "f"(f));
    return r;
}

__device__ __forceinline__ void mma8(float* c,
                                     uint32_t a0, uint32_t a1, uint32_t a2, uint32_t a3,
                                     uint32_t b0, uint32_t b1) {
    asm volatile(
        "mma.sync.aligned.m16n8k8.row.col.f32.tf32.tf32.f32 "
        "{%0,%1,%2,%3}, {%4,%5,%6,%7}, {%8,%9}, {%0,%1,%2,%3};"
        : "+f"(c[0]), "+f"(c[1]), "+f"(c[2]), "+f"(c[3])
        : "r"(a0), "r"(a1), "r"(a2), "r"(a3), "r"(b0), "r"(b1));
}

__global__ __launch_bounds__(256)
void gemm_tc(const float* __restrict__ A, const float* __restrict__ W,
             const float* __restrict__ bias, const float* __restrict__ res,
             float* __restrict__ out, float scale)
{
    __shared__ float As[BM * PADK];   // [m][k]
    __shared__ float Bs[BN * PADK];   // [n][k]

    const int row0 = blockIdx.x * BM;
    const int col0 = blockIdx.y * BN;
    const int tid  = threadIdx.x;
    const int lane = tid & 31;
    const int warp = tid >> 5;
    const int wm   = (warp & 1) * 32;   // warp row offset   (2 warps in m)
    const int wn   = (warp >> 1) * 16;  // warp col offset   (4 warps in n)
    const int g    = lane >> 2;         // fragment group id (0..7)
    const int t    = lane & 3;          // thread in group   (0..3)

    float acc[2][2][4];
    #pragma unroll
    for (int i = 0; i < 2; i++)
        #pragma unroll
        for (int j = 0; j < 2; j++)
            #pragma unroll
            for (int c = 0; c < 4; c++) acc[i][j][c] = 0.f;

    for (int k0 = 0; k0 < DD; k0 += BK) {
        // Stage A [m][k] and W [n][k], float4 per thread
        #pragma unroll
        for (int i = tid; i < BM * (BK / 4); i += 256) {
            int m  = i >> 4;
            int k4 = (i & 15) << 2;
            *(float4*)&As[m * PADK + k4] =
                *(const float4*)&A[(size_t)(row0 + m) * DD + k0 + k4];
            *(float4*)&Bs[m * PADK + k4] =
                *(const float4*)&W[(size_t)(col0 + m) * DD + k0 + k4];
        }
        __syncthreads();

        #pragma unroll
        for (int kc = 0; kc < BK; kc += 8) {
            // A fragments for 2 m-tiles, split into tf32 hi/lo
            uint32_t ahi[2][4], alo[2][4];
            #pragma unroll
            for (int mt = 0; mt < 2; mt++) {
                int r = wm + mt * 16 + g;
                float av[4];
                av[0] = As[r * PADK + kc + t];
                av[1] = As[(r + 8) * PADK + kc + t];
                av[2] = As[r * PADK + kc + t + 4];
                av[3] = As[(r + 8) * PADK + kc + t + 4];
                #pragma unroll
                for (int j = 0; j < 4; j++) {
                    ahi[mt][j] = f2tf32(av[j]);
                    alo[mt][j] = f2tf32(av[j] - __uint_as_float(ahi[mt][j]));
                }
            }
            // B fragments for 2 n-tiles
            uint32_t bhi[2][2], blo[2][2];
            #pragma unroll
            for (int nt = 0; nt < 2; nt++) {
                int n = wn + nt * 8 + g;
                float bv[2];
                bv[0] = Bs[n * PADK + kc + t];
                bv[1] = Bs[n * PADK + kc + t + 4];
                #pragma unroll
                for (int j = 0; j < 2; j++) {
                    bhi[nt][j] = f2tf32(bv[j]);
                    blo[nt][j] = f2tf32(bv[j] - __uint_as_float(bhi[nt][j]));
                }
            }
            // 3xTF32: acc += alo*bhi + ahi*blo + ahi*bhi
            #pragma unroll
            for (int mt = 0; mt < 2; mt++)
                #pragma unroll
                for (int nt = 0; nt < 2; nt++) {
                    mma8(acc[mt][nt], alo[mt][0], alo[mt][1], alo[mt][2], alo[mt][3],
                         bhi[nt][0], bhi[nt][1]);
                    mma8(acc[mt][nt], ahi[mt][0], ahi[mt][1], ahi[mt][2], ahi[mt][3],
                         blo[nt][0], blo[nt][1]);
                    mma8(acc[mt][nt], ahi[mt][0], ahi[mt][1], ahi[mt][2], ahi[mt][3],
                         bhi[nt][0], bhi[nt][1]);
                }
        }
        __syncthreads();
    }

    // Epilogue: c0,c1 -> (row, 2t / 2t+1); c2,c3 -> (row+8, same cols)
    #pragma unroll
    for (int mt = 0; mt < 2; mt++) {
        #pragma unroll
        for (int nt = 0; nt < 2; nt++) {
            int row = row0 + wm + mt * 16 + g;
            int col = col0 + wn + nt * 8 + t * 2;
            float b0 = bias[col], b1 = bias[col + 1];
            #pragma unroll
            for (int half = 0; half < 2; half++) {
                int r = row + half * 8;
                float v0 = (acc[mt][nt][half * 2 + 0] + b0) * scale;
                float v1 = (acc[mt][nt][half * 2 + 1] + b1) * scale;
                if (res != nullptr) {
                    const float2 rv = *(const float2*)&res[(size_t)r * DD + col];
                    v0 += rv.x; v1 += rv.y;
                }
                float2 o; o.x = v0; o.y = v1;
                *(float2*)&out[(size_t)r * DD + col] = o;
            }
        }
    }
}

// ---------------- banded attention: window d in [-2, 2] within each sequence
#define TS 16              // queries per block
#define KVROWS (TS + 4)    // staged key/value rows

__global__ __launch_bounds__(256)
void band_attn(const float* __restrict__ mask0)
{
    __shared__ float ks[KVROWS * DD];
    __shared__ float vs[KVROWS * DD];
    __shared__ float msk[KVROWS];

    const int chunk = blockIdx.x;
    const int b  = chunk / (SEQ / TS);
    const int s0 = (chunk % (SEQ / TS)) * TS;
    const int tid = threadIdx.x;

    for (int i4 = tid; i4 < KVROWS * (DD / 4); i4 += 256) {
        int r  = i4 / (DD / 4);
        int c4 = i4 % (DD / 4);
        int s  = s0 - 2 + r;
        float4 kv = make_float4(0.f, 0.f, 0.f, 0.f);
        float4 vv = make_float4(0.f, 0.f, 0.f, 0.f);
        if (s >= 0 && s < SEQ) {
            size_t off = (size_t)(b * SEQ + s) * DD + c4 * 4;
            kv = *(const float4*)&g_k[off];
            vv = *(const float4*)&g_v[off];
        }
        *(float4*)&ks[r * DD + c4 * 4] = kv;
        *(float4*)&vs[r * DD + c4 * 4] = vv;
    }
    if (tid < KVROWS) {
        int s = s0 - 2 + tid;
        msk[tid] = (s >= 0 && s < SEQ) ? mask0[b * SEQ + s] : 0.f;
    }
    __syncthreads();

    const int sl = tid >> 4;    // local query index 0..15
    const int h  = tid & 15;    // head
    const int s  = s0 + sl;

    float q[HDIM];
    {
        const float* qp = &g_q[(size_t)(b * SEQ + s) * DD + h * HDIM];
        float4 q0 = *(const float4*)(qp + 0);
        float4 q1 = *(const float4*)(qp + 4);
        float4 q2 = *(const float4*)(qp + 8);
        q[0]=q0.x; q[1]=q0.y; q[2]=q0.z;  q[3]=q0.w;
        q[4]=q1.x; q[5]=q1.y; q[6]=q1.z;  q[7]=q1.w;
        q[8]=q2.x; q[9]=q2.y; q[10]=q2.z; q[11]=q2.w;
    }

    const float NEG = -3.402823466e38f;            // finfo(float32).min
    const float NINF = __int_as_float(0xff800000); // -inf

    float sc[5];
    #pragma unroll
    for (int d = 0; d < 5; d++) {
        int r = sl + d;
        int skey = s + d - 2;
        const float* kp = &ks[r * DD + h * HDIM];
        float dot = 0.f;
        #pragma unroll
        for (int j = 0; j < HDIM; j++) dot += q[j] * kp[j];
        float fm = (msk[r] != 0.f) ? NEG : 0.f;
        sc[d] = (skey >= 0 && skey < SEQ) ? (dot + fm) : NINF;
    }

    float mx = sc[0];
    #pragma unroll
    for (int d = 1; d < 5; d++) mx = fmaxf(mx, sc[d]);
    float e[5], sum = 0.f;
    #pragma unroll
    for (int d = 0; d < 5; d++) { e[d] = expf(sc[d] - mx); sum += e[d]; }
    float inv = 1.f / sum;
    bool index_masked = (msk[sl + 2] < 0.f);

    float c[HDIM] = {};
    #pragma unroll
    for (int d = 0; d < 5; d++) {
        float p = index_masked ? 0.f : e[d] * inv;
        const float* vp = &vs[(sl + d) * DD + h * HDIM];
        #pragma unroll
        for (int j = 0; j < HDIM; j++) c[j] += p * vp[j];
    }

    float* op = &g_ctx[(size_t)(b * SEQ + s) * DD + h * HDIM];
    *(float4*)(op + 0) = make_float4(c[0], c[1], c[2],  c[3]);
    *(float4*)(op + 4) = make_float4(c[4], c[5], c[6],  c[7]);
    *(float4*)(op + 8) = make_float4(c[8], c[9], c[10], c[11]);
}

// ---------------- LayerNorm over the last dim (192), warp per row
__global__ __launch_bounds__(256)
void layernorm(const float* __restrict__ ln_g, const float* __restrict__ ln_b,
               float* __restrict__ out)
{
    const int row  = blockIdx.x * 8 + (threadIdx.x >> 5);
    const int lane = threadIdx.x & 31;

    const float* hp = &g_q[(size_t)row * DD];  // g_q holds h after gemm #4
    float h[6];
    float sum = 0.f;
    #pragma unroll
    for (int j = 0; j < 6; j++) { h[j] = hp[lane + j * 32]; sum += h[j]; }
    #pragma unroll
    for (int o = 16; o > 0; o >>= 1) sum += __shfl_xor_sync(0xffffffffu, sum, o);
    float mu = sum * (1.f / 192.f);

    float s2 = 0.f;
    #pragma unroll
    for (int j = 0; j < 6; j++) { float d = h[j] - mu; s2 += d * d; }
    #pragma unroll
    for (int o = 16; o > 0; o >>= 1) s2 += __shfl_xor_sync(0xffffffffu, s2, o);
    float invstd = rsqrtf(s2 * (1.f / 192.f) + 1e-12f);

    float* op = &out[(size_t)row * DD];
    #pragma unroll
    for (int j = 0; j < 6; j++) {
        int cc = lane + j * 32;
        op[cc] = (h[j] - mu) * invstd * ln_g[cc] + ln_b[cc];
    }
}

// ---------------- launch -------------------------------------------------
extern "C" void kernel_launch(void* const* d_in, const int* in_sizes, int n_in,
                              void* d_out, int out_size)
{
    const float* x     = (const float*)d_in[0];
    const float* mask0 = (const float*)d_in[1];
    const float* Wq    = (const float*)d_in[2];
    const float* bq    = (const float*)d_in[3];
    const float* Wk    = (const float*)d_in[4];
    const float* bk    = (const float*)d_in[5];
    const float* Wv    = (const float*)d_in[6];
    const float* bv    = (const float*)d_in[7];
    const float* Wo    = (const float*)d_in[8];
    const float* bo    = (const float*)d_in[9];
    const float* ln_g  = (const float*)d_in[10];
    const float* ln_b  = (const float*)d_in[11];
    float* out = (float*)d_out;

    float *pq, *pk, *pv, *pctx;
    cudaGetSymbolAddress((void**)&pq,   g_q);
    cudaGetSymbolAddress((void**)&pk,   g_k);
    cudaGetSymbolAddress((void**)&pv,   g_v);
    cudaGetSymbolAddress((void**)&pctx, g_ctx);

    const float qscale = 0.28867513459481287f;  // 1/sqrt(12)

    dim3 ggrid(NROWS / BM, DD / BN);            // (2048, 3)
    gemm_tc<<<ggrid, 256>>>(x,    Wq, bq, nullptr, pq, qscale);
    gemm_tc<<<ggrid, 256>>>(x,    Wk, bk, nullptr, pk, 1.0f);
    gemm_tc<<<ggrid, 256>>>(x,    Wv, bv, nullptr, pv, 1.0f);

    band_attn<<<BATCH * (SEQ / TS), 256>>>(mask0);

    gemm_tc<<<ggrid, 256>>>(pctx, Wo, bo, x,      pq, 1.0f);  // h -> g_q

    layernorm<<<NROWS / 8, 256>>>(ln_g, ln_b, out);
}

// round 4
// speedup vs baseline: 1.4522x; 1.1113x over previous
#include <cuda_runtime.h>
#include <math.h>
#include <stdint.h>

// Problem dims (fixed by the dataset)
#define DD    192           // hidden dim
#define HDIM  12            // head dim
#define SEQ   8192          // sequence length per batch
#define BATCH 16
#define NROWS (BATCH * SEQ) // 131072 total rows

// ---------------- scratch (static device globals; no runtime allocation) ---
__device__ float g_q[(size_t)NROWS * DD];
__device__ float g_k[(size_t)NROWS * DD];
__device__ float g_v[(size_t)NROWS * DD];
__device__ float g_ctx[(size_t)NROWS * DD];
// g_q is reused as the pre-LayerNorm buffer h after attention consumes q.

// ---------------- tensor-core GEMM (3xTF32, pre-converted smem planes) ----
// out[seg][r, c] = (sum_k A[r,k] * W[seg][c,k] + bias[seg][c]) * scale[seg]
//                  (+ res[r,c] if res)  where seg = global_col / 192.
#define BM 128
#define BN 64
#define BK 32
#define PADK 36  // smem row stride in words; (4g+t) distinct -> conflict-free

struct GemmArgs {
    const float* W[3];
    const float* bias[3];
    float*       out[3];
    float        scale[3];
    const float* res;     // residual added to segment-0 output (or nullptr)
};

__device__ __forceinline__ uint32_t f2tf32(float f) {
    uint32_t r;
    asm("cvt.rna.tf32.f32 %0, %1;" : "=r"(r) : "f"(f));
    return r;
}

__device__ __forceinline__ void mma8(float* c,
                                     uint32_t a0, uint32_t a1, uint32_t a2, uint32_t a3,
                                     uint32_t b0, uint32_t b1) {
    asm volatile(
        "mma.sync.aligned.m16n8k8.row.col.f32.tf32.tf32.f32 "
        "{%0,%1,%2,%3}, {%4,%5,%6,%7}, {%8,%9}, {%0,%1,%2,%3};"
        : "+f"(c[0]), "+f"(c[1]), "+f"(c[2]), "+f"(c[3])
        : "r"(a0), "r"(a1), "r"(a2), "r"(a3), "r"(b0), "r"(b1));
}

// 256 threads, 8 warps arranged 4(m) x 2(n); warp tile 32x32 (mt=2, nt=4).
__global__ __launch_bounds__(256, 2)
void gemm_tc(const float* __restrict__ A, GemmArgs args)
{
    extern __shared__ uint32_t smem[];
    uint32_t* Ahi = smem;                 // [128][36]
    uint32_t* Alo = Ahi + BM * PADK;
    uint32_t* Bhi = Alo + BM * PADK;      // [64][36]
    uint32_t* Blo = Bhi + BN * PADK;

    const int col0g = blockIdx.x * BN;     // global col (0..575 or 0..191)
    const int seg   = col0g / DD;
    const int lc0   = col0g - seg * DD;    // col within this weight
    const int row0  = blockIdx.y * BM;

    const float* __restrict__ W = args.W[seg];

    const int tid  = threadIdx.x;
    const int lane = tid & 31;
    const int warp = tid >> 5;
    const int wm   = (warp & 3) * 32;   // 4 warps in m
    const int wn   = (warp >> 2) * 32;  // 2 warps in n
    const int g    = lane >> 2;
    const int t    = lane & 3;

    float acc[2][4][4];
    #pragma unroll
    for (int i = 0; i < 2; i++)
        #pragma unroll
        for (int j = 0; j < 4; j++)
            #pragma unroll
            for (int c = 0; c < 4; c++) acc[i][j][c] = 0.f;

    for (int k0 = 0; k0 < DD; k0 += BK) {
        // ---- stage + convert once per element -------------------------
        #pragma unroll
        for (int i = tid; i < BM * (BK / 4); i += 256) {
            int m  = i >> 3;
            int k4 = (i & 7) << 2;
            float4 a = *(const float4*)&A[(size_t)(row0 + m) * DD + k0 + k4];
            uint4 hi, lo;
            hi.x = f2tf32(a.x); lo.x = f2tf32(a.x - __uint_as_float(hi.x));
            hi.y = f2tf32(a.y); lo.y = f2tf32(a.y - __uint_as_float(hi.y));
            hi.z = f2tf32(a.z); lo.z = f2tf32(a.z - __uint_as_float(hi.z));
            hi.w = f2tf32(a.w); lo.w = f2tf32(a.w - __uint_as_float(hi.w));
            *(uint4*)&Ahi[m * PADK + k4] = hi;
            *(uint4*)&Alo[m * PADK + k4] = lo;
        }
        #pragma unroll
        for (int i = tid; i < BN * (BK / 4); i += 256) {
            int n  = i >> 3;
            int k4 = (i & 7) << 2;
            float4 b = *(const float4*)&W[(size_t)(lc0 + n) * DD + k0 + k4];
            uint4 hi, lo;
            hi.x = f2tf32(b.x); lo.x = f2tf32(b.x - __uint_as_float(hi.x));
            hi.y = f2tf32(b.y); lo.y = f2tf32(b.y - __uint_as_float(hi.y));
            hi.z = f2tf32(b.z); lo.z = f2tf32(b.z - __uint_as_float(hi.z));
            hi.w = f2tf32(b.w); lo.w = f2tf32(b.w - __uint_as_float(hi.w));
            *(uint4*)&Bhi[n * PADK + k4] = hi;
            *(uint4*)&Blo[n * PADK + k4] = lo;
        }
        __syncthreads();

        // ---- pure LDS + MMA inner loop --------------------------------
        #pragma unroll
        for (int kc = 0; kc < BK; kc += 8) {
            uint32_t ahi[2][4], alo[2][4];
            #pragma unroll
            for (int mt = 0; mt < 2; mt++) {
                int r = wm + mt * 16 + g;
                int o0 = r * PADK + kc + t;
                int o8 = (r + 8) * PADK + kc + t;
                ahi[mt][0] = Ahi[o0];     alo[mt][0] = Alo[o0];
                ahi[mt][1] = Ahi[o8];     alo[mt][1] = Alo[o8];
                ahi[mt][2] = Ahi[o0 + 4]; alo[mt][2] = Alo[o0 + 4];
                ahi[mt][3] = Ahi[o8 + 4]; alo[mt][3] = Alo[o8 + 4];
            }
            uint32_t bhi[4][2], blo[4][2];
            #pragma unroll
            for (int nt = 0; nt < 4; nt++) {
                int o = (wn + nt * 8 + g) * PADK + kc + t;
                bhi[nt][0] = Bhi[o];     blo[nt][0] = Blo[o];
                bhi[nt][1] = Bhi[o + 4]; blo[nt][1] = Blo[o + 4];
            }
            #pragma unroll
            for (int mt = 0; mt < 2; mt++)
                #pragma unroll
                for (int nt = 0; nt < 4; nt++) {
                    mma8(acc[mt][nt], alo[mt][0], alo[mt][1], alo[mt][2], alo[mt][3],
                         bhi[nt][0], bhi[nt][1]);
                    mma8(acc[mt][nt], ahi[mt][0], ahi[mt][1], ahi[mt][2], ahi[mt][3],
                         blo[nt][0], blo[nt][1]);
                    mma8(acc[mt][nt], ahi[mt][0], ahi[mt][1], ahi[mt][2], ahi[mt][3],
                         bhi[nt][0], bhi[nt][1]);
                }
        }
        __syncthreads();
    }

    // ---- epilogue ------------------------------------------------------
    const float scale = args.scale[seg];
    float* const outp = args.out[seg];
    const float* const bias = args.bias[seg];
    const float* const res  = args.res;

    #pragma unroll
    for (int mt = 0; mt < 2; mt++) {
        #pragma unroll
        for (int nt = 0; nt < 4; nt++) {
            int row = row0 + wm + mt * 16 + g;
            int col = lc0 + wn + nt * 8 + t * 2;
            float b0 = bias[col], b1 = bias[col + 1];
            #pragma unroll
            for (int half = 0; half < 2; half++) {
                int r = row + half * 8;
                float v0 = (acc[mt][nt][half * 2 + 0] + b0) * scale;
                float v1 = (acc[mt][nt][half * 2 + 1] + b1) * scale;
                if (res != nullptr) {
                    const float2 rv = *(const float2*)&res[(size_t)r * DD + col];
                    v0 += rv.x; v1 += rv.y;
                }
                float2 o; o.x = v0; o.y = v1;
                *(float2*)&outp[(size_t)r * DD + col] = o;
            }
        }
    }
}

#define GEMM_SMEM ((BM * PADK * 2 + BN * PADK * 2) * 4)  // 55296 bytes

// ---------------- banded attention: window d in [-2, 2] within each sequence
#define TS 16              // queries per block
#define KVROWS (TS + 4)    // staged key/value rows

__global__ __launch_bounds__(256)
void band_attn(const float* __restrict__ mask0)
{
    __shared__ float ks[KVROWS * DD];
    __shared__ float vs[KVROWS * DD];
    __shared__ float msk[KVROWS];

    const int chunk = blockIdx.x;
    const int b  = chunk / (SEQ / TS);
    const int s0 = (chunk % (SEQ / TS)) * TS;
    const int tid = threadIdx.x;

    for (int i4 = tid; i4 < KVROWS * (DD / 4); i4 += 256) {
        int r  = i4 / (DD / 4);
        int c4 = i4 % (DD / 4);
        int s  = s0 - 2 + r;
        float4 kv = make_float4(0.f, 0.f, 0.f, 0.f);
        float4 vv = make_float4(0.f, 0.f, 0.f, 0.f);
        if (s >= 0 && s < SEQ) {
            size_t off = (size_t)(b * SEQ + s) * DD + c4 * 4;
            kv = *(const float4*)&g_k[off];
            vv = *(const float4*)&g_v[off];
        }
        *(float4*)&ks[r * DD + c4 * 4] = kv;
        *(float4*)&vs[r * DD + c4 * 4] = vv;
    }
    if (tid < KVROWS) {
        int s = s0 - 2 + tid;
        msk[tid] = (s >= 0 && s < SEQ) ? mask0[b * SEQ + s] : 0.f;
    }
    __syncthreads();

    const int sl = tid >> 4;    // local query index 0..15
    const int h  = tid & 15;    // head
    const int s  = s0 + sl;

    float q[HDIM];
    {
        const float* qp = &g_q[(size_t)(b * SEQ + s) * DD + h * HDIM];
        float4 q0 = *(const float4*)(qp + 0);
        float4 q1 = *(const float4*)(qp + 4);
        float4 q2 = *(const float4*)(qp + 8);
        q[0]=q0.x; q[1]=q0.y; q[2]=q0.z;  q[3]=q0.w;
        q[4]=q1.x; q[5]=q1.y; q[6]=q1.z;  q[7]=q1.w;
        q[8]=q2.x; q[9]=q2.y; q[10]=q2.z; q[11]=q2.w;
    }

    const float NEG = -3.402823466e38f;            // finfo(float32).min
    const float NINF = __int_as_float(0xff800000); // -inf

    float sc[5];
    #pragma unroll
    for (int d = 0; d < 5; d++) {
        int r = sl + d;
        int skey = s + d - 2;
        const float* kp = &ks[r * DD + h * HDIM];
        float dot = 0.f;
        #pragma unroll
        for (int j = 0; j < HDIM; j++) dot += q[j] * kp[j];
        float fm = (msk[r] != 0.f) ? NEG : 0.f;
        sc[d] = (skey >= 0 && skey < SEQ) ? (dot + fm) : NINF;
    }

    float mx = sc[0];
    #pragma unroll
    for (int d = 1; d < 5; d++) mx = fmaxf(mx, sc[d]);
    float e[5], sum = 0.f;
    #pragma unroll
    for (int d = 0; d < 5; d++) { e[d] = expf(sc[d] - mx); sum += e[d]; }
    float inv = 1.f / sum;
    bool index_masked = (msk[sl + 2] < 0.f);

    float c[HDIM] = {};
    #pragma unroll
    for (int d = 0; d < 5; d++) {
        float p = index_masked ? 0.f : e[d] * inv;
        const float* vp = &vs[(sl + d) * DD + h * HDIM];
        #pragma unroll
        for (int j = 0; j < HDIM; j++) c[j] += p * vp[j];
    }

    float* op = &g_ctx[(size_t)(b * SEQ + s) * DD + h * HDIM];
    *(float4*)(op + 0) = make_float4(c[0], c[1], c[2],  c[3]);
    *(float4*)(op + 4) = make_float4(c[4], c[5], c[6],  c[7]);
    *(float4*)(op + 8) = make_float4(c[8], c[9], c[10], c[11]);
}

// ---------------- LayerNorm over the last dim (192), warp per row
__global__ __launch_bounds__(256)
void layernorm(const float* __restrict__ ln_g, const float* __restrict__ ln_b,
               float* __restrict__ out)
{
    const int row  = blockIdx.x * 8 + (threadIdx.x >> 5);
    const int lane = threadIdx.x & 31;

    const float* hp = &g_q[(size_t)row * DD];  // g_q holds h after gemm #4
    float h[6];
    float sum = 0.f;
    #pragma unroll
    for (int j = 0; j < 6; j++) { h[j] = hp[lane + j * 32]; sum += h[j]; }
    #pragma unroll
    for (int o = 16; o > 0; o >>= 1) sum += __shfl_xor_sync(0xffffffffu, sum, o);
    float mu = sum * (1.f / 192.f);

    float s2 = 0.f;
    #pragma unroll
    for (int j = 0; j < 6; j++) { float d = h[j] - mu; s2 += d * d; }
    #pragma unroll
    for (int o = 16; o > 0; o >>= 1) s2 += __shfl_xor_sync(0xffffffffu, s2, o);
    float invstd = rsqrtf(s2 * (1.f / 192.f) + 1e-12f);

    float* op = &out[(size_t)row * DD];
    #pragma unroll
    for (int j = 0; j < 6; j++) {
        int cc = lane + j * 32;
        op[cc] = (h[j] - mu) * invstd * ln_g[cc] + ln_b[cc];
    }
}

// ---------------- launch -------------------------------------------------
extern "C" void kernel_launch(void* const* d_in, const int* in_sizes, int n_in,
                              void* d_out, int out_size)
{
    const float* x     = (const float*)d_in[0];
    const float* mask0 = (const float*)d_in[1];
    const float* Wq    = (const float*)d_in[2];
    const float* bq    = (const float*)d_in[3];
    const float* Wk    = (const float*)d_in[4];
    const float* bk    = (const float*)d_in[5];
    const float* Wv    = (const float*)d_in[6];
    const float* bv    = (const float*)d_in[7];
    const float* Wo    = (const float*)d_in[8];
    const float* bo    = (const float*)d_in[9];
    const float* ln_g  = (const float*)d_in[10];
    const float* ln_b  = (const float*)d_in[11];
    float* out = (float*)d_out;

    float *pq, *pk, *pv, *pctx;
    cudaGetSymbolAddress((void**)&pq,   g_q);
    cudaGetSymbolAddress((void**)&pk,   g_k);
    cudaGetSymbolAddress((void**)&pv,   g_v);
    cudaGetSymbolAddress((void**)&pctx, g_ctx);

    cudaFuncSetAttribute(gemm_tc, cudaFuncAttributeMaxDynamicSharedMemorySize,
                         GEMM_SMEM);

    const float qscale = 0.28867513459481287f;  // 1/sqrt(12)

    // Fused QKV: N = 576 across three weight segments; n fast in grid.x so
    // the 9 n-blocks sharing one A tile are launch-adjacent (L2 reuse).
    GemmArgs qkv;
    qkv.W[0] = Wq;  qkv.W[1] = Wk;  qkv.W[2] = Wv;
    qkv.bias[0] = bq; qkv.bias[1] = bk; qkv.bias[2] = bv;
    qkv.out[0] = pq;  qkv.out[1] = pk;  qkv.out[2] = pv;
    qkv.scale[0] = qscale; qkv.scale[1] = 1.f; qkv.scale[2] = 1.f;
    qkv.res = nullptr;
    dim3 qkv_grid(3 * DD / BN, NROWS / BM);     // (9, 1024)
    gemm_tc<<<qkv_grid, 256, GEMM_SMEM>>>(x, qkv);

    band_attn<<<BATCH * (SEQ / TS), 256>>>(mask0);

    // Output projection + residual -> g_q (becomes h)
    GemmArgs og;
    og.W[0] = Wo; og.W[1] = Wo; og.W[2] = Wo;
    og.bias[0] = bo; og.bias[1] = bo; og.bias[2] = bo;
    og.out[0] = pq; og.out[1] = pq; og.out[2] = pq;
    og.scale[0] = 1.f; og.scale[1] = 1.f; og.scale[2] = 1.f;
    og.res = x;
    dim3 o_grid(DD / BN, NROWS / BM);           // (3, 1024)
    gemm_tc<<<o_grid, 256, GEMM_SMEM>>>(pctx, og);

    layernorm<<<NROWS / 8, 256>>>(ln_g, ln_b, out);
}

// round 6
// speedup vs baseline: 1.9143x; 1.3182x over previous
#include <cuda_runtime.h>
#include <cuda_bf16.h>
#include <math.h>
#include <stdint.h>

// Problem dims (fixed by the dataset)
#define DD    192
#define HDIM  12
#define SEQ   8192
#define BATCH 16
#define NROWS (BATCH * SEQ)
#define WELTS (DD * DD)       // 36864 elements per weight

// ---------------- scratch (static device globals) -------------------------
__device__ float g_q[(size_t)NROWS * DD];
__device__ float g_k[(size_t)NROWS * DD];
__device__ float g_v[(size_t)NROWS * DD];
__device__ float g_ctx[(size_t)NROWS * DD];
// bf16 hi/lo planes for Wq,Wk,Wv,Wo: plane index = w*2 + (0=hi,1=lo)
__device__ __nv_bfloat16 g_wsplit[(size_t)8 * WELTS];

// ---------------- helpers --------------------------------------------------
__device__ __forceinline__ uint32_t pack_bf2(__nv_bfloat16 a, __nv_bfloat16 b) {
    return (uint32_t)__bfloat16_as_ushort(a) |
           ((uint32_t)__bfloat16_as_ushort(b) << 16);
}
__device__ __forceinline__ void split2(float x, __nv_bfloat16& hi, __nv_bfloat16& lo) {
    hi = __float2bfloat16(x);
    lo = __float2bfloat16(x - __bfloat162float(hi));
}

// bf16 m16n8k16 mma, fp32 accumulate
__device__ __forceinline__ void mma16(float* c, const uint32_t* a, const uint32_t* b) {
    asm volatile(
        "mma.sync.aligned.m16n8k16.row.col.f32.bf16.bf16.f32 "
        "{%0,%1,%2,%3}, {%4,%5,%6,%7}, {%8,%9}, {%0,%1,%2,%3};"
        : "+f"(c[0]), "+f"(c[1]), "+f"(c[2]), "+f"(c[3])
        : "r"(a[0]), "r"(a[1]), "r"(a[2]), "r"(a[3]), "r"(b[0]), "r"(b[1]));
}

// ---------------- prep: split 4 weights into bf16 hi/lo planes -------------
__global__ __launch_bounds__(256)
void split_weights(const float* __restrict__ Wq, const float* __restrict__ Wk,
                   const float* __restrict__ Wv, const float* __restrict__ Wo)
{
    int f = blockIdx.x * 256 + threadIdx.x;     // float4 index
    int w  = f / (WELTS / 4);
    int e4 = (f - w * (WELTS / 4)) * 4;
    const float* W = (w == 0) ? Wq : (w == 1) ? Wk : (w == 2) ? Wv : Wo;
    float4 a = *(const float4*)&W[e4];
    __nv_bfloat16 h0,h1,h2,h3,l0,l1,l2,l3;
    split2(a.x,h0,l0); split2(a.y,h1,l1); split2(a.z,h2,l2); split2(a.w,h3,l3);
    uint2 hp, lp;
    hp.x = pack_bf2(h0,h1); hp.y = pack_bf2(h2,h3);
    lp.x = pack_bf2(l0,l1); lp.y = pack_bf2(l2,l3);
    *(uint2*)&g_wsplit[(size_t)(w*2)   * WELTS + e4] = hp;
    *(uint2*)&g_wsplit[(size_t)(w*2+1) * WELTS + e4] = lp;
}

// ---------------- GEMM: bf16 3-split on legacy mma (m16n8k16) --------------
// out[seg][r, c] = (sum_k A[r,k] * W[seg][c,k] + bias[seg][c]) * scale[seg]
//                  (+ res[r,c] if res)  where seg = global_col / 64 / 3.
#define BM 128
#define BN 64
#define BK 32
#define PADW 20  // uint32 (bf16-pair) row stride: 16 pairs + 4 pad; banks distinct

struct GemmArgs {
    int          plane[3];  // hi plane index in g_wsplit (lo = +1)
    const float* bias[3];
    float*       out[3];
    float        scale[3];
    const float* res;
};

__global__ __launch_bounds__(256)
void gemm_bf16(const float* __restrict__ A, GemmArgs args)
{
    __shared__ uint32_t Ahi[BM * PADW];  // [m][kpair]
    __shared__ uint32_t Alo[BM * PADW];
    __shared__ uint32_t Bhi[BN * PADW];  // [n][kpair]
    __shared__ uint32_t Blo[BN * PADW];

    const int col0g = blockIdx.x * BN;
    const int seg   = col0g / DD;
    const int lc0   = col0g - seg * DD;
    const int row0  = blockIdx.y * BM;

    const __nv_bfloat16* __restrict__ Wh = g_wsplit + (size_t)args.plane[seg] * WELTS;
    const __nv_bfloat16* __restrict__ Wl = Wh + WELTS;

    const int tid  = threadIdx.x;
    const int lane = tid & 31;
    const int warp = tid >> 5;
    const int wm   = (warp & 3) * 32;   // 4 warps in m
    const int wn   = (warp >> 2) * 32;  // 2 warps in n
    const int g    = lane >> 2;         // 0..7
    const int t    = lane & 3;          // 0..3

    float acc[2][4][4];
    #pragma unroll
    for (int i = 0; i < 2; i++)
        #pragma unroll
        for (int j = 0; j < 4; j++)
            #pragma unroll
            for (int c = 0; c < 4; c++) acc[i][j][c] = 0.f;

    for (int k0 = 0; k0 < DD; k0 += BK) {
        // ---- stage A: fp32 -> bf16 hi/lo packed pairs ---------------------
        #pragma unroll
        for (int it = 0; it < 4; it++) {
            int idx = tid + it * 256;          // 0..1023
            int m   = idx >> 3;
            int k4  = (idx & 7) << 2;
            float4 a = *(const float4*)&A[(size_t)(row0 + m) * DD + k0 + k4];
            __nv_bfloat16 h0,h1,h2,h3,l0,l1,l2,l3;
            split2(a.x,h0,l0); split2(a.y,h1,l1);
            split2(a.z,h2,l2); split2(a.w,h3,l3);
            uint2 hp, lp;
            hp.x = pack_bf2(h0,h1); hp.y = pack_bf2(h2,h3);
            lp.x = pack_bf2(l0,l1); lp.y = pack_bf2(l2,l3);
            int dst = m * PADW + (k4 >> 1);
            *(uint2*)&Ahi[dst] = hp;
            *(uint2*)&Alo[dst] = lp;
        }
        // ---- stage B: copy pre-split planes ------------------------------
        {
            int n  = tid >> 2;                 // 0..63
            int k8 = (tid & 3) << 3;           // 0,8,16,24
            int dst = n * PADW + (k8 >> 1);
            *(uint4*)&Bhi[dst] = *(const uint4*)&Wh[(size_t)(lc0 + n) * DD + k0 + k8];
            *(uint4*)&Blo[dst] = *(const uint4*)&Wl[(size_t)(lc0 + n) * DD + k0 + k8];
        }
        __syncthreads();

        // ---- 2 k16 steps per chunk ---------------------------------------
        #pragma unroll
        for (int ks = 0; ks < 2; ks++) {
            const int kpb = ks * 8;
            uint32_t ah[2][4], al[2][4];
            #pragma unroll
            for (int mt = 0; mt < 2; mt++) {
                int o = (wm + mt * 16 + g) * PADW + kpb + t;
                ah[mt][0] = Ahi[o];               al[mt][0] = Alo[o];
                ah[mt][1] = Ahi[o + 8 * PADW];    al[mt][1] = Alo[o + 8 * PADW];
                ah[mt][2] = Ahi[o + 4];           al[mt][2] = Alo[o + 4];
                ah[mt][3] = Ahi[o + 8 * PADW + 4];al[mt][3] = Alo[o + 8 * PADW + 4];
            }
            uint32_t bh[4][2], bl[4][2];
            #pragma unroll
            for (int nt = 0; nt < 4; nt++) {
                int o = (wn + nt * 8 + g) * PADW + kpb + t;
                bh[nt][0] = Bhi[o];     bl[nt][0] = Blo[o];
                bh[nt][1] = Bhi[o + 4]; bl[nt][1] = Blo[o + 4];
            }
            #pragma unroll
            for (int mt = 0; mt < 2; mt++)
                #pragma unroll
                for (int nt = 0; nt < 4; nt++) {
                    mma16(acc[mt][nt], al[mt], bh[nt]);
                    mma16(acc[mt][nt], ah[mt], bl[nt]);
                    mma16(acc[mt][nt], ah[mt], bh[nt]);
                }
        }
        __syncthreads();
    }

    // ---- epilogue ----------------------------------------------------------
    const float scale = args.scale[seg];
    float* const outp = args.out[seg];
    const float* const bias = args.bias[seg];
    const float* const res  = args.res;

    #pragma unroll
    for (int mt = 0; mt < 2; mt++) {
        #pragma unroll
        for (int nt = 0; nt < 4; nt++) {
            int row = row0 + wm + mt * 16 + g;
            int col = lc0 + wn + nt * 8 + t * 2;
            float b0 = bias[col], b1 = bias[col + 1];
            #pragma unroll
            for (int half = 0; half < 2; half++) {
                int r = row + half * 8;
                float v0 = (acc[mt][nt][half * 2 + 0] + b0) * scale;
                float v1 = (acc[mt][nt][half * 2 + 1] + b1) * scale;
                if (res != nullptr) {
                    const float2 rv = *(const float2*)&res[(size_t)r * DD + col];
                    v0 += rv.x; v1 += rv.y;
                }
                float2 o; o.x = v0; o.y = v1;
                *(float2*)&outp[(size_t)r * DD + col] = o;
            }
        }
    }
}

// ---------------- banded attention (unchanged, verified) -------------------
#define TS 16
#define KVROWS (TS + 4)

__global__ __launch_bounds__(256)
void band_attn(const float* __restrict__ mask0)
{
    __shared__ float ks[KVROWS * DD];
    __shared__ float vs[KVROWS * DD];
    __shared__ float msk[KVROWS];

    const int chunk = blockIdx.x;
    const int b  = chunk / (SEQ / TS);
    const int s0 = (chunk % (SEQ / TS)) * TS;
    const int tid = threadIdx.x;

    for (int i4 = tid; i4 < KVROWS * (DD / 4); i4 += 256) {
        int r  = i4 / (DD / 4);
        int c4 = i4 % (DD / 4);
        int s  = s0 - 2 + r;
        float4 kv = make_float4(0.f, 0.f, 0.f, 0.f);
        float4 vv = make_float4(0.f, 0.f, 0.f, 0.f);
        if (s >= 0 && s < SEQ) {
            size_t off = (size_t)(b * SEQ + s) * DD + c4 * 4;
            kv = *(const float4*)&g_k[off];
            vv = *(const float4*)&g_v[off];
        }
        *(float4*)&ks[r * DD + c4 * 4] = kv;
        *(float4*)&vs[r * DD + c4 * 4] = vv;
    }
    if (tid < KVROWS) {
        int s = s0 - 2 + tid;
        msk[tid] = (s >= 0 && s < SEQ) ? mask0[b * SEQ + s] : 0.f;
    }
    __syncthreads();

    const int sl = tid >> 4;
    const int h  = tid & 15;
    const int s  = s0 + sl;

    float q[HDIM];
    {
        const float* qp = &g_q[(size_t)(b * SEQ + s) * DD + h * HDIM];
        float4 q0 = *(const float4*)(qp + 0);
        float4 q1 = *(const float4*)(qp + 4);
        float4 q2 = *(const float4*)(qp + 8);
        q[0]=q0.x; q[1]=q0.y; q[2]=q0.z;  q[3]=q0.w;
        q[4]=q1.x; q[5]=q1.y; q[6]=q1.z;  q[7]=q1.w;
        q[8]=q2.x; q[9]=q2.y; q[10]=q2.z; q[11]=q2.w;
    }

    const float NEG  = -3.402823466e38f;
    const float NINF = __int_as_float(0xff800000);

    float sc[5];
    #pragma unroll
    for (int d = 0; d < 5; d++) {
        int r = sl + d;
        int skey = s + d - 2;
        const float* kp = &ks[r * DD + h * HDIM];
        float dot = 0.f;
        #pragma unroll
        for (int j = 0; j < HDIM; j++) dot += q[j] * kp[j];
        float fm = (msk[r] != 0.f) ? NEG : 0.f;
        sc[d] = (skey >= 0 && skey < SEQ) ? (dot + fm) : NINF;
    }

    float mx = sc[0];
    #pragma unroll
    for (int d = 1; d < 5; d++) mx = fmaxf(mx, sc[d]);
    float e[5], sum = 0.f;
    #pragma unroll
    for (int d = 0; d < 5; d++) { e[d] = expf(sc[d] - mx); sum += e[d]; }
    float inv = 1.f / sum;
    bool index_masked = (msk[sl + 2] < 0.f);

    float c[HDIM] = {};
    #pragma unroll
    for (int d = 0; d < 5; d++) {
        float p = index_masked ? 0.f : e[d] * inv;
        const float* vp = &vs[(sl + d) * DD + h * HDIM];
        #pragma unroll
        for (int j = 0; j < HDIM; j++) c[j] += p * vp[j];
    }

    float* op = &g_ctx[(size_t)(b * SEQ + s) * DD + h * HDIM];
    *(float4*)(op + 0) = make_float4(c[0], c[1], c[2],  c[3]);
    *(float4*)(op + 4) = make_float4(c[4], c[5], c[6],  c[7]);
    *(float4*)(op + 8) = make_float4(c[8], c[9], c[10], c[11]);
}

// ---------------- LayerNorm over the last dim (192), warp per row ----------
__global__ __launch_bounds__(256)
void layernorm(const float* __restrict__ ln_g, const float* __restrict__ ln_b,
               float* __restrict__ out)
{
    const int row  = blockIdx.x * 8 + (threadIdx.x >> 5);
    const int lane = threadIdx.x & 31;

    const float* hp = &g_q[(size_t)row * DD];  // g_q holds h after O-proj
    float h[6];
    float sum = 0.f;
    #pragma unroll
    for (int j = 0; j < 6; j++) { h[j] = hp[lane + j * 32]; sum += h[j]; }
    #pragma unroll
    for (int o = 16; o > 0; o >>= 1) sum += __shfl_xor_sync(0xffffffffu, sum, o);
    float mu = sum * (1.f / 192.f);

    float s2 = 0.f;
    #pragma unroll
    for (int j = 0; j < 6; j++) { float d = h[j] - mu; s2 += d * d; }
    #pragma unroll
    for (int o = 16; o > 0; o >>= 1) s2 += __shfl_xor_sync(0xffffffffu, s2, o);
    float invstd = rsqrtf(s2 * (1.f / 192.f) + 1e-12f);

    float* op = &out[(size_t)row * DD];
    #pragma unroll
    for (int j = 0; j < 6; j++) {
        int cc = lane + j * 32;
        op[cc] = (h[j] - mu) * invstd * ln_g[cc] + ln_b[cc];
    }
}

// ---------------- launch ---------------------------------------------------
extern "C" void kernel_launch(void* const* d_in, const int* in_sizes, int n_in,
                              void* d_out, int out_size)
{
    const float* x     = (const float*)d_in[0];
    const float* mask0 = (const float*)d_in[1];
    const float* bq    = (const float*)d_in[3];
    const float* bk    = (const float*)d_in[5];
    const float* bv    = (const float*)d_in[7];
    const float* bo    = (const float*)d_in[9];
    const float* ln_g  = (const float*)d_in[10];
    const float* ln_b  = (const float*)d_in[11];
    float* out = (float*)d_out;

    float *pq, *pk, *pv, *pctx;
    cudaGetSymbolAddress((void**)&pq,   g_q);
    cudaGetSymbolAddress((void**)&pk,   g_k);
    cudaGetSymbolAddress((void**)&pv,   g_v);
    cudaGetSymbolAddress((void**)&pctx, g_ctx);

    const float qscale = 0.28867513459481287f;  // 1/sqrt(12)

    split_weights<<<WELTS / 256, 256>>>((const float*)d_in[2], (const float*)d_in[4],
                                        (const float*)d_in[6], (const float*)d_in[8]);

    // Fused QKV: 9 n-blocks (3 segs x 3 cols), n fast for L2 reuse of x rows
    GemmArgs qkv;
    qkv.plane[0] = 0; qkv.plane[1] = 2; qkv.plane[2] = 4;
    qkv.bias[0] = bq; qkv.bias[1] = bk; qkv.bias[2] = bv;
    qkv.out[0] = pq;  qkv.out[1] = pk;  qkv.out[2] = pv;
    qkv.scale[0] = qscale; qkv.scale[1] = 1.f; qkv.scale[2] = 1.f;
    qkv.res = nullptr;
    dim3 qkv_grid(3 * DD / BN, NROWS / BM);     // (9, 1024)
    gemm_bf16<<<qkv_grid, 256>>>(x, qkv);

    band_attn<<<BATCH * (SEQ / TS), 256>>>(mask0);

    // Output projection + residual -> g_q (becomes h)
    GemmArgs og;
    og.plane[0] = 6; og.plane[1] = 6; og.plane[2] = 6;
    og.bias[0] = bo; og.bias[1] = bo; og.bias[2] = bo;
    og.out[0] = pq; og.out[1] = pq; og.out[2] = pq;
    og.scale[0] = 1.f; og.scale[1] = 1.f; og.scale[2] = 1.f;
    og.res = x;
    dim3 o_grid(DD / BN, NROWS / BM);           // (3, 1024)
    gemm_bf16<<<o_grid, 256>>>(pctx, og);

    layernorm<<<NROWS / 8, 256>>>(ln_g, ln_b, out);
}

// round 8
// speedup vs baseline: 1.9212x; 1.0036x over previous
#include <cuda_runtime.h>
#include <cuda_bf16.h>
#include <math.h>
#include <stdint.h>

// Problem dims (fixed by the dataset)
#define DD    192
#define HDIM  12
#define SEQ   8192
#define BATCH 16
#define NROWS (BATCH * SEQ)
#define WELTS (DD * DD)         // 36864 elements per weight
#define APLANE ((size_t)NROWS * DD)

// ---------------- scratch (static device globals) -------------------------
__device__ float g_q[(size_t)NROWS * DD];
__device__ float g_k[(size_t)NROWS * DD];
__device__ float g_v[(size_t)NROWS * DD];
// bf16 hi/lo planes (plane 0 = hi at offset 0, plane 1 = lo at +APLANE)
__device__ __nv_bfloat16 g_xsplit[(size_t)2 * NROWS * DD];
__device__ __nv_bfloat16 g_ctxsplit[(size_t)2 * NROWS * DD];
// bf16 hi/lo planes for Wq,Wk,Wv,Wo: plane index = w*2 + (0=hi,1=lo)
__device__ __nv_bfloat16 g_wsplit[(size_t)8 * WELTS];

// ---------------- helpers --------------------------------------------------
__device__ __forceinline__ uint32_t pack_bf2(__nv_bfloat16 a, __nv_bfloat16 b) {
    return (uint32_t)__bfloat16_as_ushort(a) |
           ((uint32_t)__bfloat16_as_ushort(b) << 16);
}
__device__ __forceinline__ void split2(float x, __nv_bfloat16& hi, __nv_bfloat16& lo) {
    hi = __float2bfloat16(x);
    lo = __float2bfloat16(x - __bfloat162float(hi));
}

// bf16 m16n8k16 mma, fp32 accumulate
__device__ __forceinline__ void mma16(float* c, const uint32_t* a, const uint32_t* b) {
    asm volatile(
        "mma.sync.aligned.m16n8k16.row.col.f32.bf16.bf16.f32 "
        "{%0,%1,%2,%3}, {%4,%5,%6,%7}, {%8,%9}, {%0,%1,%2,%3};"
        : "+f"(c[0]), "+f"(c[1]), "+f"(c[2]), "+f"(c[3])
        : "r"(a[0]), "r"(a[1]), "r"(a[2]), "r"(a[3]), "r"(b[0]), "r"(b[1]));
}

// ---------------- prep: split weights / activations ------------------------
__global__ __launch_bounds__(256)
void split_weights(const float* __restrict__ Wq, const float* __restrict__ Wk,
                   const float* __restrict__ Wv, const float* __restrict__ Wo)
{
    int f = blockIdx.x * 256 + threadIdx.x;     // float4 index
    int w  = f / (WELTS / 4);
    int e4 = (f - w * (WELTS / 4)) * 4;
    const float* W = (w == 0) ? Wq : (w == 1) ? Wk : (w == 2) ? Wv : Wo;
    float4 a = *(const float4*)&W[e4];
    __nv_bfloat16 h0,h1,h2,h3,l0,l1,l2,l3;
    split2(a.x,h0,l0); split2(a.y,h1,l1); split2(a.z,h2,l2); split2(a.w,h3,l3);
    uint2 hp, lp;
    hp.x = pack_bf2(h0,h1); hp.y = pack_bf2(h2,h3);
    lp.x = pack_bf2(l0,l1); lp.y = pack_bf2(l2,l3);
    *(uint2*)&g_wsplit[(size_t)(w*2)   * WELTS + e4] = hp;
    *(uint2*)&g_wsplit[(size_t)(w*2+1) * WELTS + e4] = lp;
}

__global__ __launch_bounds__(256)
void split_x(const float* __restrict__ x)
{
    size_t f = (size_t)blockIdx.x * 256 + threadIdx.x;   // float4 index
    float4 a = ((const float4*)x)[f];
    __nv_bfloat16 h0,h1,h2,h3,l0,l1,l2,l3;
    split2(a.x,h0,l0); split2(a.y,h1,l1); split2(a.z,h2,l2); split2(a.w,h3,l3);
    uint2 hp, lp;
    hp.x = pack_bf2(h0,h1); hp.y = pack_bf2(h2,h3);
    lp.x = pack_bf2(l0,l1); lp.y = pack_bf2(l2,l3);
    ((uint2*)g_xsplit)[f] = hp;
    ((uint2*)(g_xsplit + APLANE))[f] = lp;
}

// ---------------- GEMM: bf16 3-split, double-buffered pipeline -------------
// out[seg][r, c] = (sum_k A[r,k] * W[seg][c,k] + bias[seg][c]) * scale[seg]
//                  (+ res[r,c] if res)  where seg = blockIdx.x / 3.
#define BM 128
#define BN 64
#define BK 32
#define PADW 20                    // uint32 (bf16-pair) row stride
#define SM_AH 0
#define SM_AL (BM * PADW)          // 2560
#define SM_BH (2 * BM * PADW)      // 5120
#define SM_BL (2 * BM * PADW + BN * PADW)
#define BUFW  (2 * BM * PADW + 2 * BN * PADW)   // 7680 uint32 per buffer
#define GEMM_SMEM (2 * BUFW * 4)                // 61440 bytes

struct GemmArgs {
    int          plane[3];  // hi plane index in g_wsplit (lo = +1)
    const float* bias[3];
    float*       out[3];
    float        scale[3];
    const float* res;
};

__global__ __launch_bounds__(256, 2)
void gemm_bf16(const __nv_bfloat16* __restrict__ Abase, GemmArgs args)
{
    extern __shared__ uint32_t smem[];          // 2 * BUFW

    const int col0g = blockIdx.x * BN;
    const int seg   = col0g / DD;
    const int lc0   = col0g - seg * DD;
    const int row0  = blockIdx.y * BM;

    const uint4* __restrict__ A4 = (const uint4*)Abase;            // 24 uint4/row
    const uint4* __restrict__ W4 =
        (const uint4*)(g_wsplit + (size_t)args.plane[seg] * WELTS);

    const int tid  = threadIdx.x;
    const int lane = tid & 31;
    const int warp = tid >> 5;
    const int wm   = (warp & 3) * 32;   // 4 warps in m
    const int wn   = (warp >> 2) * 32;  // 2 warps in n
    const int g    = lane >> 2;
    const int t    = lane & 3;

    float acc[2][4][4];
    #pragma unroll
    for (int i = 0; i < 2; i++)
        #pragma unroll
        for (int j = 0; j < 4; j++)
            #pragma unroll
            for (int c = 0; c < 4; c++) acc[i][j][c] = 0.f;

    // ---- staging helpers (pure copies; planes pre-converted) --------------
    auto load_chunk = [&](int c, uint4* na, uint4* nb) {
        #pragma unroll
        for (int i = 0; i < 4; i++) {
            int idx = tid + i * 256;
            int pl = idx >> 9, rem = idx & 511;
            int m = rem >> 2, q4 = rem & 3;
            na[i] = A4[(size_t)pl * (APLANE / 8) + (size_t)(row0 + m) * 24 + c * 4 + q4];
        }
        #pragma unroll
        for (int i = 0; i < 2; i++) {
            int idx = tid + i * 256;
            int pl = idx >> 8, rem = idx & 255;
            int n = rem >> 2, q4 = rem & 3;
            nb[i] = W4[(size_t)pl * (WELTS / 8) + (size_t)(lc0 + n) * 24 + c * 4 + q4];
        }
    };
    auto store_chunk = [&](uint32_t* buf, const uint4* na, const uint4* nb) {
        #pragma unroll
        for (int i = 0; i < 4; i++) {
            int idx = tid + i * 256;
            int pl = idx >> 9, rem = idx & 511;
            int m = rem >> 2, q4 = rem & 3;
            *(uint4*)&buf[(pl ? SM_AL : SM_AH) + m * PADW + q4 * 4] = na[i];
        }
        #pragma unroll
        for (int i = 0; i < 2; i++) {
            int idx = tid + i * 256;
            int pl = idx >> 8, rem = idx & 255;
            int n = rem >> 2, q4 = rem & 3;
            *(uint4*)&buf[(pl ? SM_BL : SM_BH) + n * PADW + q4 * 4] = nb[i];
        }
    };

    // ---- prologue ----------------------------------------------------------
    {
        uint4 pa[4], pb[2];
        load_chunk(0, pa, pb);
        store_chunk(smem, pa, pb);
    }
    __syncthreads();

    // ---- pipelined main loop over 6 chunks ---------------------------------
    #pragma unroll
    for (int c = 0; c < 6; c++) {
        uint32_t* cur = smem + (c & 1) * BUFW;
        uint32_t* nxt = smem + ((c + 1) & 1) * BUFW;
        uint4 na[4], nb[2];
        if (c < 5) load_chunk(c + 1, na, nb);

        #pragma unroll
        for (int ks = 0; ks < 2; ks++) {
            const int kpb = ks * 8;
            uint32_t ah[2][4], al[2][4];
            #pragma unroll
            for (int mt = 0; mt < 2; mt++) {
                int o = (wm + mt * 16 + g) * PADW + kpb + t;
                ah[mt][0] = cur[SM_AH + o];
                ah[mt][1] = cur[SM_AH + o + 8 * PADW];
                ah[mt][2] = cur[SM_AH + o + 4];
                ah[mt][3] = cur[SM_AH + o + 8 * PADW + 4];
                al[mt][0] = cur[SM_AL + o];
                al[mt][1] = cur[SM_AL + o + 8 * PADW];
                al[mt][2] = cur[SM_AL + o + 4];
                al[mt][3] = cur[SM_AL + o + 8 * PADW + 4];
            }
            uint32_t bh[4][2], bl[4][2];
            #pragma unroll
            for (int nt = 0; nt < 4; nt++) {
                int o = (wn + nt * 8 + g) * PADW + kpb + t;
                bh[nt][0] = cur[SM_BH + o];
                bh[nt][1] = cur[SM_BH + o + 4];
                bl[nt][0] = cur[SM_BL + o];
                bl[nt][1] = cur[SM_BL + o + 4];
            }
            #pragma unroll
            for (int mt = 0; mt < 2; mt++)
                #pragma unroll
                for (int nt = 0; nt < 4; nt++) {
                    mma16(acc[mt][nt], al[mt], bh[nt]);
                    mma16(acc[mt][nt], ah[mt], bl[nt]);
                    mma16(acc[mt][nt], ah[mt], bh[nt]);
                }
        }

        if (c < 5) store_chunk(nxt, na, nb);
        __syncthreads();
    }

    // ---- epilogue ----------------------------------------------------------
    const float scale = args.scale[seg];
    float* const outp = args.out[seg];
    const float* const bias = args.bias[seg];
    const float* const res  = args.res;

    #pragma unroll
    for (int mt = 0; mt < 2; mt++) {
        #pragma unroll
        for (int nt = 0; nt < 4; nt++) {
            int row = row0 + wm + mt * 16 + g;
            int col = lc0 + wn + nt * 8 + t * 2;
            float b0 = bias[col], b1 = bias[col + 1];
            #pragma unroll
            for (int half = 0; half < 2; half++) {
                int r = row + half * 8;
                float v0 = (acc[mt][nt][half * 2 + 0] + b0) * scale;
                float v1 = (acc[mt][nt][half * 2 + 1] + b1) * scale;
                if (res != nullptr) {
                    const float2 rv = *(const float2*)&res[(size_t)r * DD + col];
                    v0 += rv.x; v1 += rv.y;
                }
                float2 o; o.x = v0; o.y = v1;
                *(float2*)&outp[(size_t)r * DD + col] = o;
            }
        }
    }
}

// ---------------- banded attention: window d in [-2, 2] --------------------
#define TS 16
#define KVROWS (TS + 4)

__global__ __launch_bounds__(256)
void band_attn(const float* __restrict__ mask0)
{
    __shared__ float ks[KVROWS * DD];
    __shared__ float vs[KVROWS * DD];
    __shared__ float msk[KVROWS];

    const int chunk = blockIdx.x;
    const int b  = chunk / (SEQ / TS);
    const int s0 = (chunk % (SEQ / TS)) * TS;
    const int tid = threadIdx.x;

    for (int i4 = tid; i4 < KVROWS * (DD / 4); i4 += 256) {
        int r  = i4 / (DD / 4);
        int c4 = i4 % (DD / 4);
        int s  = s0 - 2 + r;
        float4 kv = make_float4(0.f, 0.f, 0.f, 0.f);
        float4 vv = make_float4(0.f, 0.f, 0.f, 0.f);
        if (s >= 0 && s < SEQ) {
            size_t off = (size_t)(b * SEQ + s) * DD + c4 * 4;
            kv = *(const float4*)&g_k[off];
            vv = *(const float4*)&g_v[off];
        }
        *(float4*)&ks[r * DD + c4 * 4] = kv;
        *(float4*)&vs[r * DD + c4 * 4] = vv;
    }
    if (tid < KVROWS) {
        int s = s0 - 2 + tid;
        msk[tid] = (s >= 0 && s < SEQ) ? mask0[b * SEQ + s] : 0.f;
    }
    __syncthreads();

    const int sl = tid >> 4;
    const int h  = tid & 15;
    const int s  = s0 + sl;

    float q[HDIM];
    {
        const float* qp = &g_q[(size_t)(b * SEQ + s) * DD + h * HDIM];
        float4 q0 = *(const float4*)(qp + 0);
        float4 q1 = *(const float4*)(qp + 4);
        float4 q2 = *(const float4*)(qp + 8);
        q[0]=q0.x; q[1]=q0.y; q[2]=q0.z;  q[3]=q0.w;
        q[4]=q1.x; q[5]=q1.y; q[6]=q1.z;  q[7]=q1.w;
        q[8]=q2.x; q[9]=q2.y; q[10]=q2.z; q[11]=q2.w;
    }

    const float NEG  = -3.402823466e38f;
    const float NINF = __int_as_float(0xff800000);

    float sc[5];
    #pragma unroll
    for (int d = 0; d < 5; d++) {
        int r = sl + d;
        int skey = s + d - 2;
        const float* kp = &ks[r * DD + h * HDIM];
        float dot = 0.f;
        #pragma unroll
        for (int j = 0; j < HDIM; j++) dot += q[j] * kp[j];
        float fm = (msk[r] != 0.f) ? NEG : 0.f;
        sc[d] = (skey >= 0 && skey < SEQ) ? (dot + fm) : NINF;
    }

    float mx = sc[0];
    #pragma unroll
    for (int d = 1; d < 5; d++) mx = fmaxf(mx, sc[d]);
    float e[5], sum = 0.f;
    #pragma unroll
    for (int d = 0; d < 5; d++) { e[d] = expf(sc[d] - mx); sum += e[d]; }
    float inv = 1.f / sum;
    bool index_masked = (msk[sl + 2] < 0.f);

    float c[HDIM] = {};
    #pragma unroll
    for (int d = 0; d < 5; d++) {
        float p = index_masked ? 0.f : e[d] * inv;
        const float* vp = &vs[(sl + d) * DD + h * HDIM];
        #pragma unroll
        for (int j = 0; j < HDIM; j++) c[j] += p * vp[j];
    }

    // write ctx directly as bf16 hi/lo planes for the O-projection
    // HDIM = 12 bf16 values = 6 packed uint32 per plane
    __nv_bfloat16 chi[HDIM], clo[HDIM];
    #pragma unroll
    for (int j = 0; j < HDIM; j++) split2(c[j], chi[j], clo[j]);
    size_t base = (size_t)(b * SEQ + s) * DD + h * HDIM;
    uint32_t* oh = (uint32_t*)(g_ctxsplit + base);
    uint32_t* ol = (uint32_t*)(g_ctxsplit + APLANE + base);
    #pragma unroll
    for (int j = 0; j < 6; j++) {
        oh[j] = pack_bf2(chi[2*j], chi[2*j+1]);
        ol[j] = pack_bf2(clo[2*j], clo[2*j+1]);
    }
}

// ---------------- LayerNorm over the last dim (192), warp per row ----------
__global__ __launch_bounds__(256)
void layernorm(const float* __restrict__ ln_g, const float* __restrict__ ln_b,
               float* __restrict__ out)
{
    const int row  = blockIdx.x * 8 + (threadIdx.x >> 5);
    const int lane = threadIdx.x & 31;

    const float* hp = &g_q[(size_t)row * DD];  // g_q holds h after O-proj
    float h[6];
    float sum = 0.f;
    #pragma unroll
    for (int j = 0; j < 6; j++) { h[j] = hp[lane + j * 32]; sum += h[j]; }
    #pragma unroll
    for (int o = 16; o > 0; o >>= 1) sum += __shfl_xor_sync(0xffffffffu, sum, o);
    float mu = sum * (1.f / 192.f);

    float s2 = 0.f;
    #pragma unroll
    for (int j = 0; j < 6; j++) { float d = h[j] - mu; s2 += d * d; }
    #pragma unroll
    for (int o = 16; o > 0; o >>= 1) s2 += __shfl_xor_sync(0xffffffffu, s2, o);
    float invstd = rsqrtf(s2 * (1.f / 192.f) + 1e-12f);

    float* op = &out[(size_t)row * DD];
    #pragma unroll
    for (int j = 0; j < 6; j++) {
        int cc = lane + j * 32;
        op[cc] = (h[j] - mu) * invstd * ln_g[cc] + ln_b[cc];
    }
}

// ---------------- launch ---------------------------------------------------
extern "C" void kernel_launch(void* const* d_in, const int* in_sizes, int n_in,
                              void* d_out, int out_size)
{
    const float* x     = (const float*)d_in[0];
    const float* mask0 = (const float*)d_in[1];
    const float* bq    = (const float*)d_in[3];
    const float* bk    = (const float*)d_in[5];
    const float* bv    = (const float*)d_in[7];
    const float* bo    = (const float*)d_in[9];
    const float* ln_g  = (const float*)d_in[10];
    const float* ln_b  = (const float*)d_in[11];
    float* out = (float*)d_out;

    float *pq, *pk, *pv;
    __nv_bfloat16 *pxs, *pcs;
    cudaGetSymbolAddress((void**)&pq,  g_q);
    cudaGetSymbolAddress((void**)&pk,  g_k);
    cudaGetSymbolAddress((void**)&pv,  g_v);
    cudaGetSymbolAddress((void**)&pxs, g_xsplit);
    cudaGetSymbolAddress((void**)&pcs, g_ctxsplit);

    cudaFuncSetAttribute(gemm_bf16, cudaFuncAttributeMaxDynamicSharedMemorySize,
                         GEMM_SMEM);

    const float qscale = 0.28867513459481287f;  // 1/sqrt(12)

    split_weights<<<WELTS / 256, 256>>>((const float*)d_in[2], (const float*)d_in[4],
                                        (const float*)d_in[6], (const float*)d_in[8]);
    split_x<<<NROWS * DD / 4 / 256, 256>>>(x);

    // Fused QKV: 9 n-blocks (3 segs x 3 cols), n fast for L2 reuse of A rows
    GemmArgs qkv;
    qkv.plane[0] = 0; qkv.plane[1] = 2; qkv.plane[2] = 4;
    qkv.bias[0] = bq; qkv.bias[1] = bk; qkv.bias[2] = bv;
    qkv.out[0] = pq;  qkv.out[1] = pk;  qkv.out[2] = pv;
    qkv.scale[0] = qscale; qkv.scale[1] = 1.f; qkv.scale[2] = 1.f;
    qkv.res = nullptr;
    dim3 qkv_grid(3 * DD / BN, NROWS / BM);     // (9, 1024)
    gemm_bf16<<<qkv_grid, 256, GEMM_SMEM>>>(pxs, qkv);

    band_attn<<<BATCH * (SEQ / TS), 256>>>(mask0);

    // Output projection + residual -> g_q (becomes h)
    GemmArgs og;
    og.plane[0] = 6; og.plane[1] = 6; og.plane[2] = 6;
    og.bias[0] = bo; og.bias[1] = bo; og.bias[2] = bo;
    og.out[0] = pq; og.out[1] = pq; og.out[2] = pq;
    og.scale[0] = 1.f; og.scale[1] = 1.f; og.scale[2] = 1.f;
    og.res = x;
    dim3 o_grid(DD / BN, NROWS / BM);           // (3, 1024)
    gemm_bf16<<<o_grid, 256, GEMM_SMEM>>>(pcs, og);

    layernorm<<<NROWS / 8, 256>>>(ln_g, ln_b, out);
}